// round 1
// baseline (speedup 1.0000x reference)
#include <cuda_runtime.h>

#define E_EDGES 320000
#define NTHR 128
#define NBLK (E_EDGES / NTHR)

// Scratch (device globals -- no allocation allowed)
__device__ __align__(16) float g_h [E_EDGES * 20];   // hidden state
__device__ __align__(16) float g_v0[E_EDGES * 32];   // v = h @ W1b (double buffered)
__device__ __align__(16) float g_v1[E_EDGES * 32];

__device__ __forceinline__ float selu_f(float x) {
    float ex  = __expf(x);
    float neg = 1.7580993408473766f * (ex - 1.0f);   // scale*alpha
    return x > 0.0f ? 1.0507009873554805f * x : neg;
}
__device__ __forceinline__ float sigmoid_f(float x) {
    return 1.0f / (1.0f + __expf(-x));
}
__device__ __forceinline__ float tanh_f(float x) {
    float xc = fminf(fmaxf(x, -15.0f), 15.0f);
    float e2 = __expf(2.0f * xc);
    return (e2 - 1.0f) / (e2 + 1.0f);
}

// dot of a 20-float shared-memory row (16B aligned) with a register array
__device__ __forceinline__ float dot20(const float* __restrict__ w, const float* a) {
    float acc = 0.0f;
    const float4* w4 = (const float4*)w;
#pragma unroll
    for (int q = 0; q < 5; q++) {
        float4 ww = w4[q];
        acc = fmaf(a[q*4+0], ww.x, acc);
        acc = fmaf(a[q*4+1], ww.y, acc);
        acc = fmaf(a[q*4+2], ww.z, acc);
        acc = fmaf(a[q*4+3], ww.w, acc);
    }
    return acc;
}

// ---------------------------------------------------------------------------
// init: v0[e] = edge_attr[e] @ W1[20:40]   (no bias)
// ---------------------------------------------------------------------------
__global__ void __launch_bounds__(NTHR) kv_init(const float* __restrict__ ea,
                                                const float* __restrict__ W1) {
    __shared__ __align__(16) float sW1b[640];
    for (int i = threadIdx.x; i < 640; i += NTHR) sW1b[i] = W1[640 + i];
    __syncthreads();

    int e = blockIdx.x * NTHR + threadIdx.x;
    float h[20];
    const float4* hp = (const float4*)(ea + (size_t)e * 20);
#pragma unroll
    for (int q = 0; q < 5; q++) {
        float4 t = hp[q];
        h[q*4+0]=t.x; h[q*4+1]=t.y; h[q*4+2]=t.z; h[q*4+3]=t.w;
    }
    float v[32];
#pragma unroll
    for (int c = 0; c < 32; c++) v[c] = 0.0f;
#pragma unroll
    for (int f = 0; f < 20; f++) {
        float hf = h[f];
        const float4* w4 = (const float4*)(sW1b + f*32);
#pragma unroll
        for (int q = 0; q < 8; q++) {
            float4 w = w4[q];
            v[q*4+0]=fmaf(hf,w.x,v[q*4+0]); v[q*4+1]=fmaf(hf,w.y,v[q*4+1]);
            v[q*4+2]=fmaf(hf,w.z,v[q*4+2]); v[q*4+3]=fmaf(hf,w.w,v[q*4+3]);
        }
    }
    float4* vp = (float4*)(g_v0 + (size_t)e * 32);
#pragma unroll
    for (int q = 0; q < 8; q++)
        vp[q] = make_float4(v[q*4], v[q*4+1], v[q*4+2], v[q*4+3]);
}

// ---------------------------------------------------------------------------
// one GRU message-passing step (fused): u, gather+selu+sum, W2, GRU, v-tail
//  parity: 0 -> read g_v0 write g_v1 ; 1 -> read g_v1 write g_v0
// ---------------------------------------------------------------------------
template<bool FIRST, bool COMPV>
__global__ void __launch_bounds__(NTHR) step_kernel(
    const float* __restrict__ ea,
    const float* __restrict__ W1,  const float* __restrict__ b1,
    const float* __restrict__ W2,  const float* __restrict__ b2,
    const float* __restrict__ Wih, const float* __restrict__ Whh,
    const float* __restrict__ bih, const float* __restrict__ bhh,
    const int*   __restrict__ dstv,
    int parity)
{
    __shared__ __align__(16) float sW1a[640];   // [f][c] 20x32
    __shared__ __align__(16) float sW1b[640];   // for v-tail
    __shared__ __align__(16) float sW2 [640];   // [c][o] 32x20
    __shared__ __align__(16) float sWih[1200];  // [o][f] 60x20
    __shared__ __align__(16) float sWhh[1200];
    __shared__ float sb1[32], sb2x16[20], sbih[60], sbhh[60];
    __shared__ float sbuf[NTHR * 33];           // u, then s (padded rows)

    const int tid = threadIdx.x;
    for (int i = tid; i < 640;  i += NTHR) sW1a[i] = W1[i];
    if (COMPV) for (int i = tid; i < 640; i += NTHR) sW1b[i] = W1[640 + i];
    for (int i = tid; i < 640;  i += NTHR) sW2[i]  = W2[i];
    for (int i = tid; i < 1200; i += NTHR) { sWih[i] = Wih[i]; sWhh[i] = Whh[i]; }
    if (tid < 32) sb1[tid] = b1[tid];
    if (tid < 20) sb2x16[tid] = 16.0f * b2[tid];
    if (tid < 60) { sbih[tid] = bih[tid]; sbhh[tid] = bhh[tid]; }
    __syncthreads();

    const float* vin  = parity ? g_v1 : g_v0;
    float*       vout = parity ? g_v0 : g_v1;
    const float* hin  = FIRST ? ea : g_h;

    const int e = blockIdx.x * NTHR + tid;

    // ---- phase 1: load own h row, compute u = h@W1a + b1, stash in shared
    float h[20];
    {
        const float4* hp = (const float4*)(hin + (size_t)e * 20);
#pragma unroll
        for (int q = 0; q < 5; q++) {
            float4 t = hp[q];
            h[q*4+0]=t.x; h[q*4+1]=t.y; h[q*4+2]=t.z; h[q*4+3]=t.w;
        }
    }
    {
        float u[32];
#pragma unroll
        for (int c = 0; c < 32; c++) u[c] = sb1[c];
#pragma unroll
        for (int f = 0; f < 20; f++) {
            float hf = h[f];
            const float4* w4 = (const float4*)(sW1a + f*32);
#pragma unroll
            for (int q = 0; q < 8; q++) {
                float4 w = w4[q];
                u[q*4+0]=fmaf(hf,w.x,u[q*4+0]); u[q*4+1]=fmaf(hf,w.y,u[q*4+1]);
                u[q*4+2]=fmaf(hf,w.z,u[q*4+2]); u[q*4+3]=fmaf(hf,w.w,u[q*4+3]);
            }
        }
#pragma unroll
        for (int c = 0; c < 32; c++) sbuf[tid*33 + c] = u[c];
    }
    __syncwarp();

    // ---- phase 2: warp-per-edge gather of 16 neighbor v rows; s = sum selu(u+v)
    {
        const int lane  = tid & 31;
        const int wbase = tid & ~31;                 // warp * 32
        const int eb    = blockIdx.x * NTHR + wbase;
#pragma unroll 1
        for (int t = 0; t < 32; t++) {
            int node = __ldg(dstv + eb + t);
            const float* vrow = vin + (size_t)node * 512 + lane;
            float uu  = sbuf[(wbase + t)*33 + lane];
            float acc = 0.0f;
#pragma unroll
            for (int k = 0; k < 16; k++)
                acc += selu_f(uu + __ldg(vrow + k*32));
            sbuf[(wbase + t)*33 + lane] = acc;       // same slot: no hazard
        }
    }
    __syncwarp();

    // ---- phase 3: agg = s@W2 + 16*b2
    float agg[20];
#pragma unroll
    for (int o = 0; o < 20; o++) agg[o] = sb2x16[o];
#pragma unroll
    for (int c = 0; c < 32; c++) {
        float sc = sbuf[tid*33 + c];
        const float4* w4 = (const float4*)(sW2 + c*20);
#pragma unroll
        for (int q = 0; q < 5; q++) {
            float4 w = w4[q];
            agg[q*4+0]=fmaf(sc,w.x,agg[q*4+0]); agg[q*4+1]=fmaf(sc,w.y,agg[q*4+1]);
            agg[q*4+2]=fmaf(sc,w.z,agg[q*4+2]); agg[q*4+3]=fmaf(sc,w.w,agg[q*4+3]);
        }
    }

    // ---- GRU
    float hnew[20];
#pragma unroll
    for (int o = 0; o < 20; o++) {
        float ir  = sbih[o]      + dot20(sWih + o*20,        agg);
        float iz  = sbih[20+o]   + dot20(sWih + (20+o)*20,   agg);
        float inn = sbih[40+o]   + dot20(sWih + (40+o)*20,   agg);
        float hr  = sbhh[o]      + dot20(sWhh + o*20,        h);
        float hz  = sbhh[20+o]   + dot20(sWhh + (20+o)*20,   h);
        float hn  = sbhh[40+o]   + dot20(sWhh + (40+o)*20,   h);
        float r = sigmoid_f(ir + hr);
        float z = sigmoid_f(iz + hz);
        float n = tanh_f(inn + r * hn);
        hnew[o] = (1.0f - z) * n + z * h[o];
    }
    {
        float4* op = (float4*)(g_h + (size_t)e * 20);
#pragma unroll
        for (int q = 0; q < 5; q++)
            op[q] = make_float4(hnew[q*4], hnew[q*4+1], hnew[q*4+2], hnew[q*4+3]);
    }

    // ---- tail: v for the NEXT step (own-row only; kernel boundary = sync)
    if (COMPV) {
        float v[32];
#pragma unroll
        for (int c = 0; c < 32; c++) v[c] = 0.0f;
#pragma unroll
        for (int f = 0; f < 20; f++) {
            float hf = hnew[f];
            const float4* w4 = (const float4*)(sW1b + f*32);
#pragma unroll
            for (int q = 0; q < 8; q++) {
                float4 w = w4[q];
                v[q*4+0]=fmaf(hf,w.x,v[q*4+0]); v[q*4+1]=fmaf(hf,w.y,v[q*4+1]);
                v[q*4+2]=fmaf(hf,w.z,v[q*4+2]); v[q*4+3]=fmaf(hf,w.w,v[q*4+3]);
            }
        }
        float4* vp = (float4*)(vout + (size_t)e * 32);
#pragma unroll
        for (int q = 0; q < 8; q++)
            vp[q] = make_float4(v[q*4], v[q*4+1], v[q*4+2], v[q*4+3]);
    }
}

// ---------------------------------------------------------------------------
// readout: selu(h@W1+b1) -> selu(@W2+b2) -> softplus(@W3+b3) + 0.1, clip
// ---------------------------------------------------------------------------
__global__ void __launch_bounds__(NTHR) readout_kernel(
    const float* __restrict__ rW1, const float* __restrict__ rb1,
    const float* __restrict__ rW2, const float* __restrict__ rb2,
    const float* __restrict__ rW3, const float* __restrict__ rb3,
    float* __restrict__ out)
{
    __shared__ __align__(16) float sW1[20*64];
    __shared__ __align__(16) float sW2[64*32];
    __shared__ float sW3[32], sb1[64], sb2[32], sb3;

    const int tid = threadIdx.x;
    for (int i = tid; i < 20*64; i += NTHR) sW1[i] = rW1[i];
    for (int i = tid; i < 64*32; i += NTHR) sW2[i] = rW2[i];
    if (tid < 32) { sW3[tid] = rW3[tid]; sb2[tid] = rb2[tid]; }
    if (tid < 64) sb1[tid] = rb1[tid];
    if (tid == 0) sb3 = rb3[0];
    __syncthreads();

    const int e = blockIdx.x * NTHR + tid;
    float h[20];
    const float4* hp = (const float4*)(g_h + (size_t)e * 20);
#pragma unroll
    for (int q = 0; q < 5; q++) {
        float4 t = hp[q];
        h[q*4+0]=t.x; h[q*4+1]=t.y; h[q*4+2]=t.z; h[q*4+3]=t.w;
    }

    float x1[64];
#pragma unroll
    for (int o = 0; o < 64; o++) x1[o] = sb1[o];
#pragma unroll
    for (int f = 0; f < 20; f++) {
        float hf = h[f];
        const float4* w4 = (const float4*)(sW1 + f*64);
#pragma unroll
        for (int q = 0; q < 16; q++) {
            float4 w = w4[q];
            x1[q*4+0]=fmaf(hf,w.x,x1[q*4+0]); x1[q*4+1]=fmaf(hf,w.y,x1[q*4+1]);
            x1[q*4+2]=fmaf(hf,w.z,x1[q*4+2]); x1[q*4+3]=fmaf(hf,w.w,x1[q*4+3]);
        }
    }
#pragma unroll
    for (int o = 0; o < 64; o++) x1[o] = selu_f(x1[o]);

    float x2[32];
#pragma unroll
    for (int o = 0; o < 32; o++) x2[o] = sb2[o];
#pragma unroll
    for (int f = 0; f < 64; f++) {
        float xf = x1[f];
        const float4* w4 = (const float4*)(sW2 + f*32);
#pragma unroll
        for (int q = 0; q < 8; q++) {
            float4 w = w4[q];
            x2[q*4+0]=fmaf(xf,w.x,x2[q*4+0]); x2[q*4+1]=fmaf(xf,w.y,x2[q*4+1]);
            x2[q*4+2]=fmaf(xf,w.z,x2[q*4+2]); x2[q*4+3]=fmaf(xf,w.w,x2[q*4+3]);
        }
    }

    float y = sb3;
#pragma unroll
    for (int c = 0; c < 32; c++) y = fmaf(selu_f(x2[c]), sW3[c], y);

    float sp = (y > 20.0f) ? y : log1pf(__expf(y));
    float w  = sp + 0.1f;
    out[e] = fminf(fmaxf(w, 0.1f), 10.0f);
}

// ---------------------------------------------------------------------------
extern "C" void kernel_launch(void* const* d_in, const int* in_sizes, int n_in,
                              void* d_out, int out_size) {
    const float* ea  = (const float*)d_in[0];
    const float* W1  = (const float*)d_in[1];
    const float* b1  = (const float*)d_in[2];
    const float* W2  = (const float*)d_in[3];
    const float* b2  = (const float*)d_in[4];
    const float* Wih = (const float*)d_in[5];
    const float* Whh = (const float*)d_in[6];
    const float* bih = (const float*)d_in[7];
    const float* bhh = (const float*)d_in[8];
    const float* rW1 = (const float*)d_in[9];
    const float* rb1 = (const float*)d_in[10];
    const float* rW2 = (const float*)d_in[11];
    const float* rb2 = (const float*)d_in[12];
    const float* rW3 = (const float*)d_in[13];
    const float* rb3 = (const float*)d_in[14];
    const int*   eix = (const int*)d_in[15];
    const int*   dst = eix + E_EDGES;            // edge_index row 1
    float* out = (float*)d_out;

    kv_init<<<NBLK, NTHR>>>(ea, W1);
    step_kernel<true,  true ><<<NBLK, NTHR>>>(ea, W1,b1,W2,b2,Wih,Whh,bih,bhh,dst, 0);
    step_kernel<false, true ><<<NBLK, NTHR>>>(ea, W1,b1,W2,b2,Wih,Whh,bih,bhh,dst, 1);
    step_kernel<false, true ><<<NBLK, NTHR>>>(ea, W1,b1,W2,b2,Wih,Whh,bih,bhh,dst, 0);
    step_kernel<false, false><<<NBLK, NTHR>>>(ea, W1,b1,W2,b2,Wih,Whh,bih,bhh,dst, 1);
    readout_kernel<<<NBLK, NTHR>>>(rW1,rb1,rW2,rb2,rW3,rb3, out);
}

// round 2
// speedup vs baseline: 1.1712x; 1.1712x over previous
#include <cuda_runtime.h>

typedef unsigned long long u64;

#define E_EDGES 320000
#define NTHR 128
#define NBLK (E_EDGES / NTHR)
#define SB_STRIDE 34   // even -> 8B-aligned rows for STS.64

// Scratch (device globals -- no allocation allowed)
__device__ __align__(16) float g_h [E_EDGES * 20];   // hidden state
__device__ __align__(16) float g_v0[E_EDGES * 32];   // v = h @ W1b (double buffered)
__device__ __align__(16) float g_v1[E_EDGES * 32];

// ---- packed f32x2 helpers (sm_103a FFMA2 path) ----
__device__ __forceinline__ u64 fma2(u64 a, u64 b, u64 c) {
    u64 d; asm("fma.rn.f32x2 %0, %1, %2, %3;" : "=l"(d) : "l"(a), "l"(b), "l"(c)); return d;
}
__device__ __forceinline__ u64 pack2(float x, float y) {
    u64 d; asm("mov.b64 %0, {%1, %2};" : "=l"(d) : "f"(x), "f"(y)); return d;
}
__device__ __forceinline__ float2 unpack2(u64 v) {
    float2 r; asm("mov.b64 {%0, %1}, %2;" : "=f"(r.x), "=f"(r.y) : "l"(v)); return r;
}

__device__ __forceinline__ float selu_f(float x) {
    float ex  = __expf(x);
    float neg = 1.7580993408473766f * (ex - 1.0f);   // scale*alpha
    return x > 0.0f ? 1.0507009873554805f * x : neg;
}
__device__ __forceinline__ float sigmoid_f(float x) {
    return 1.0f / (1.0f + __expf(-x));
}
__device__ __forceinline__ float tanh_f(float x) {
    float xc = fminf(fmaxf(x, -15.0f), 15.0f);
    float e2 = __expf(2.0f * xc);
    return (e2 - 1.0f) / (e2 + 1.0f);
}

// packed dot of a 20-float 16B-aligned shared row with packed array a[10]
__device__ __forceinline__ float dot20p(const float* __restrict__ w, const u64* a) {
    const ulonglong2* w2 = (const ulonglong2*)w;
    u64 acc0 = 0ull, acc1 = 0ull;   // bits of (+0,+0)
#pragma unroll
    for (int q = 0; q < 5; q++) {
        ulonglong2 ww = w2[q];
        acc0 = fma2(a[2*q],   ww.x, acc0);
        acc1 = fma2(a[2*q+1], ww.y, acc1);
    }
    float2 r0 = unpack2(acc0), r1 = unpack2(acc1);
    return (r0.x + r0.y) + (r1.x + r1.y);
}

// packed matvec: acc2[16] (32 outs) += hf * w_row[32], row 16B-aligned
__device__ __forceinline__ void mv32p(u64* acc2, float hf, const float* __restrict__ wrow) {
    u64 h2 = pack2(hf, hf);
    const ulonglong2* w = (const ulonglong2*)wrow;
#pragma unroll
    for (int q = 0; q < 8; q++) {
        ulonglong2 ww = w[q];
        acc2[2*q]   = fma2(h2, ww.x, acc2[2*q]);
        acc2[2*q+1] = fma2(h2, ww.y, acc2[2*q+1]);
    }
}

// ---------------------------------------------------------------------------
// init: v0[e] = edge_attr[e] @ W1[20:40]   (no bias)
// ---------------------------------------------------------------------------
__global__ void __launch_bounds__(NTHR) kv_init(const float* __restrict__ ea,
                                                const float* __restrict__ W1) {
    __shared__ __align__(16) float sW1b[640];
    for (int i = threadIdx.x; i < 640; i += NTHR) sW1b[i] = W1[640 + i];
    __syncthreads();

    int e = blockIdx.x * NTHR + threadIdx.x;
    u64 h2[10];
    {
        const ulonglong2* hp = (const ulonglong2*)(ea + (size_t)e * 20);
#pragma unroll
        for (int q = 0; q < 5; q++) { ulonglong2 t = hp[q]; h2[2*q] = t.x; h2[2*q+1] = t.y; }
    }
    u64 v2[16];
#pragma unroll
    for (int c = 0; c < 16; c++) v2[c] = 0ull;
#pragma unroll
    for (int fp = 0; fp < 10; fp++) {
        float2 hh = unpack2(h2[fp]);
        mv32p(v2, hh.x, sW1b + (2*fp)   * 32);
        mv32p(v2, hh.y, sW1b + (2*fp+1) * 32);
    }
    ulonglong2* vp = (ulonglong2*)(g_v0 + (size_t)e * 32);
#pragma unroll
    for (int q = 0; q < 8; q++) { ulonglong2 t; t.x = v2[2*q]; t.y = v2[2*q+1]; vp[q] = t; }
}

// ---------------------------------------------------------------------------
// one GRU message-passing step (fused): u, gather+selu+sum, W2, GRU, v-tail
// ---------------------------------------------------------------------------
template<bool FIRST, bool COMPV>
__global__ void __launch_bounds__(NTHR, 6) step_kernel(
    const float* __restrict__ ea,
    const float* __restrict__ W1,  const float* __restrict__ b1,
    const float* __restrict__ W2,  const float* __restrict__ b2,
    const float* __restrict__ Wih, const float* __restrict__ Whh,
    const float* __restrict__ bih, const float* __restrict__ bhh,
    const int*   __restrict__ dstv,
    int parity)
{
    __shared__ __align__(16) float sW1a[640];   // [f][c] 20x32
    __shared__ __align__(16) float sW1b[640];   // for v-tail
    __shared__ __align__(16) float sW2 [640];   // [c][o] 32x20
    __shared__ __align__(16) float sWih[1200];  // [o][f] 60x20
    __shared__ __align__(16) float sWhh[1200];
    __shared__ __align__(16) float sb1[32];
    __shared__ __align__(16) float sb2x16[20];
    __shared__ float sbih[60], sbhh[60];
    __shared__ __align__(16) float sbuf[NTHR * SB_STRIDE];  // u, then s

    const int tid = threadIdx.x;
    for (int i = tid; i < 640;  i += NTHR) sW1a[i] = W1[i];
    if (COMPV) for (int i = tid; i < 640; i += NTHR) sW1b[i] = W1[640 + i];
    for (int i = tid; i < 640;  i += NTHR) sW2[i]  = W2[i];
    for (int i = tid; i < 1200; i += NTHR) { sWih[i] = Wih[i]; sWhh[i] = Whh[i]; }
    if (tid < 32) sb1[tid] = b1[tid];
    if (tid < 20) sb2x16[tid] = 16.0f * b2[tid];
    if (tid < 60) { sbih[tid] = bih[tid]; sbhh[tid] = bhh[tid]; }
    __syncthreads();

    const float* vin  = parity ? g_v1 : g_v0;
    float*       vout = parity ? g_v0 : g_v1;
    const float* hin  = FIRST ? ea : g_h;

    const int e = blockIdx.x * NTHR + tid;

    // ---- own h row (packed)
    u64 h2[10];
    {
        const ulonglong2* hp = (const ulonglong2*)(hin + (size_t)e * 20);
#pragma unroll
        for (int q = 0; q < 5; q++) { ulonglong2 t = hp[q]; h2[2*q] = t.x; h2[2*q+1] = t.y; }
    }

    // ---- phase 1: u = h@W1a + b1  -> sbuf (STS.64)
    {
        u64 u2[16];
        const ulonglong2* bp = (const ulonglong2*)sb1;
#pragma unroll
        for (int q = 0; q < 8; q++) { ulonglong2 t = bp[q]; u2[2*q] = t.x; u2[2*q+1] = t.y; }
#pragma unroll
        for (int fp = 0; fp < 10; fp++) {
            float2 hh = unpack2(h2[fp]);
            mv32p(u2, hh.x, sW1a + (2*fp)   * 32);
            mv32p(u2, hh.y, sW1a + (2*fp+1) * 32);
        }
        u64* sp = (u64*)(sbuf + tid * SB_STRIDE);
#pragma unroll
        for (int c = 0; c < 16; c++) sp[c] = u2[c];
    }
    __syncwarp();

    // ---- phase 2: warp-per-edge gather of 16 neighbor v rows; s = sum selu(u+v)
    {
        const int lane  = tid & 31;
        const int wbase = tid & ~31;
        const int eb    = blockIdx.x * NTHR + wbase;
        const int mydst = __ldg(dstv + eb + lane);
#pragma unroll 1
        for (int t = 0; t < 32; t++) {
            int node = __shfl_sync(0xffffffffu, mydst, t);
            const float* vrow = vin + (size_t)node * 512 + lane;
            float uu = sbuf[(wbase + t) * SB_STRIDE + lane];
            float a0 = 0.0f, a1 = 0.0f;
#pragma unroll
            for (int k = 0; k < 16; k += 2) {
                a0 += selu_f(uu + __ldg(vrow + k * 32));
                a1 += selu_f(uu + __ldg(vrow + (k + 1) * 32));
            }
            sbuf[(wbase + t) * SB_STRIDE + lane] = a0 + a1;
        }
    }
    __syncwarp();

    // ---- phase 3: agg = s@W2 + 16*b2  (packed accumulators)
    u64 agg2[10];
    {
        const ulonglong2* bp = (const ulonglong2*)sb2x16;
#pragma unroll
        for (int q = 0; q < 5; q++) { ulonglong2 t = bp[q]; agg2[2*q] = t.x; agg2[2*q+1] = t.y; }
#pragma unroll
        for (int c = 0; c < 32; c++) {
            float sc = sbuf[tid * SB_STRIDE + c];
            u64 sc2 = pack2(sc, sc);
            const ulonglong2* w = (const ulonglong2*)(sW2 + c * 20);
#pragma unroll
            for (int q = 0; q < 5; q++) {
                ulonglong2 ww = w[q];
                agg2[2*q]   = fma2(sc2, ww.x, agg2[2*q]);
                agg2[2*q+1] = fma2(sc2, ww.y, agg2[2*q+1]);
            }
        }
    }

    // ---- GRU (packed dots), process outputs in pairs to share h unpack
    float hnew[20];
#pragma unroll
    for (int op = 0; op < 10; op++) {
        float2 hh = unpack2(h2[op]);
#pragma unroll
        for (int j = 0; j < 2; j++) {
            int o = 2 * op + j;
            float hval = j ? hh.y : hh.x;
            float ir  = dot20p(sWih + o*20,        agg2) + sbih[o];
            float iz  = dot20p(sWih + (20+o)*20,   agg2) + sbih[20+o];
            float inn = dot20p(sWih + (40+o)*20,   agg2) + sbih[40+o];
            float hr  = dot20p(sWhh + o*20,        h2)   + sbhh[o];
            float hz  = dot20p(sWhh + (20+o)*20,   h2)   + sbhh[20+o];
            float hn  = dot20p(sWhh + (40+o)*20,   h2)   + sbhh[40+o];
            float r = sigmoid_f(ir + hr);
            float z = sigmoid_f(iz + hz);
            float n = tanh_f(inn + r * hn);
            hnew[o] = (1.0f - z) * n + z * hval;
        }
    }
    {
        float4* opn = (float4*)(g_h + (size_t)e * 20);
#pragma unroll
        for (int q = 0; q < 5; q++)
            opn[q] = make_float4(hnew[q*4], hnew[q*4+1], hnew[q*4+2], hnew[q*4+3]);
    }

    // ---- tail: v for the NEXT step
    if (COMPV) {
        u64 v2[16];
#pragma unroll
        for (int c = 0; c < 16; c++) v2[c] = 0ull;
#pragma unroll
        for (int f = 0; f < 20; f++)
            mv32p(v2, hnew[f], sW1b + f * 32);
        ulonglong2* vp = (ulonglong2*)(vout + (size_t)e * 32);
#pragma unroll
        for (int q = 0; q < 8; q++) { ulonglong2 t; t.x = v2[2*q]; t.y = v2[2*q+1]; vp[q] = t; }
    }
}

// ---------------------------------------------------------------------------
// readout: selu(h@W1+b1) -> selu(@W2+b2) -> softplus(@W3+b3) + 0.1, clip
// ---------------------------------------------------------------------------
__global__ void __launch_bounds__(NTHR) readout_kernel(
    const float* __restrict__ rW1, const float* __restrict__ rb1,
    const float* __restrict__ rW2, const float* __restrict__ rb2,
    const float* __restrict__ rW3, const float* __restrict__ rb3,
    float* __restrict__ out)
{
    __shared__ __align__(16) float sW1[20*64];
    __shared__ __align__(16) float sW2[64*32];
    __shared__ __align__(16) float sW3[32];
    __shared__ __align__(16) float sb1[64];
    __shared__ __align__(16) float sb2[32];
    __shared__ float sb3;

    const int tid = threadIdx.x;
    for (int i = tid; i < 20*64; i += NTHR) sW1[i] = rW1[i];
    for (int i = tid; i < 64*32; i += NTHR) sW2[i] = rW2[i];
    if (tid < 32) { sW3[tid] = rW3[tid]; sb2[tid] = rb2[tid]; }
    if (tid < 64) sb1[tid] = rb1[tid];
    if (tid == 0) sb3 = rb3[0];
    __syncthreads();

    const int e = blockIdx.x * NTHR + tid;
    float h[20];
    {
        const float4* hp = (const float4*)(g_h + (size_t)e * 20);
#pragma unroll
        for (int q = 0; q < 5; q++) {
            float4 t = hp[q];
            h[q*4+0]=t.x; h[q*4+1]=t.y; h[q*4+2]=t.z; h[q*4+3]=t.w;
        }
    }

    // layer 1: 20 -> 64 (packed accumulators: 32 pairs)
    u64 x12[32];
    {
        const ulonglong2* bp = (const ulonglong2*)sb1;
#pragma unroll
        for (int q = 0; q < 16; q++) { ulonglong2 t = bp[q]; x12[2*q] = t.x; x12[2*q+1] = t.y; }
#pragma unroll
        for (int f = 0; f < 20; f++) {
            u64 hf2 = pack2(h[f], h[f]);
            const ulonglong2* w = (const ulonglong2*)(sW1 + f * 64);
#pragma unroll
            for (int q = 0; q < 16; q++) {
                ulonglong2 ww = w[q];
                x12[2*q]   = fma2(hf2, ww.x, x12[2*q]);
                x12[2*q+1] = fma2(hf2, ww.y, x12[2*q+1]);
            }
        }
    }
    float x1[64];
#pragma unroll
    for (int p = 0; p < 32; p++) {
        float2 t = unpack2(x12[p]);
        x1[2*p]   = selu_f(t.x);
        x1[2*p+1] = selu_f(t.y);
    }

    // layer 2: 64 -> 32 (packed)
    u64 x22[16];
    {
        const ulonglong2* bp = (const ulonglong2*)sb2;
#pragma unroll
        for (int q = 0; q < 8; q++) { ulonglong2 t = bp[q]; x22[2*q] = t.x; x22[2*q+1] = t.y; }
#pragma unroll
        for (int f = 0; f < 64; f++) {
            u64 xf2 = pack2(x1[f], x1[f]);
            const ulonglong2* w = (const ulonglong2*)(sW2 + f * 32);
#pragma unroll
            for (int q = 0; q < 8; q++) {
                ulonglong2 ww = w[q];
                x22[2*q]   = fma2(xf2, ww.x, x22[2*q]);
                x22[2*q+1] = fma2(xf2, ww.y, x22[2*q+1]);
            }
        }
    }

    float y = sb3;
#pragma unroll
    for (int p = 0; p < 16; p++) {
        float2 t = unpack2(x22[p]);
        y = fmaf(selu_f(t.x), sW3[2*p],   y);
        y = fmaf(selu_f(t.y), sW3[2*p+1], y);
    }

    float sp = (y > 20.0f) ? y : log1pf(__expf(y));
    float w  = sp + 0.1f;
    out[e] = fminf(fmaxf(w, 0.1f), 10.0f);
}

// ---------------------------------------------------------------------------
extern "C" void kernel_launch(void* const* d_in, const int* in_sizes, int n_in,
                              void* d_out, int out_size) {
    const float* ea  = (const float*)d_in[0];
    const float* W1  = (const float*)d_in[1];
    const float* b1  = (const float*)d_in[2];
    const float* W2  = (const float*)d_in[3];
    const float* b2  = (const float*)d_in[4];
    const float* Wih = (const float*)d_in[5];
    const float* Whh = (const float*)d_in[6];
    const float* bih = (const float*)d_in[7];
    const float* bhh = (const float*)d_in[8];
    const float* rW1 = (const float*)d_in[9];
    const float* rb1 = (const float*)d_in[10];
    const float* rW2 = (const float*)d_in[11];
    const float* rb2 = (const float*)d_in[12];
    const float* rW3 = (const float*)d_in[13];
    const float* rb3 = (const float*)d_in[14];
    const int*   eix = (const int*)d_in[15];
    const int*   dst = eix + E_EDGES;            // edge_index row 1
    float* out = (float*)d_out;

    kv_init<<<NBLK, NTHR>>>(ea, W1);
    step_kernel<true,  true ><<<NBLK, NTHR>>>(ea, W1,b1,W2,b2,Wih,Whh,bih,bhh,dst, 0);
    step_kernel<false, true ><<<NBLK, NTHR>>>(ea, W1,b1,W2,b2,Wih,Whh,bih,bhh,dst, 1);
    step_kernel<false, true ><<<NBLK, NTHR>>>(ea, W1,b1,W2,b2,Wih,Whh,bih,bhh,dst, 0);
    step_kernel<false, false><<<NBLK, NTHR>>>(ea, W1,b1,W2,b2,Wih,Whh,bih,bhh,dst, 1);
    readout_kernel<<<NBLK, NTHR>>>(rW1,rb1,rW2,rb2,rW3,rb3, out);
}